// round 7
// baseline (speedup 1.0000x reference)
#include <cuda_runtime.h>
#include <cuda_bf16.h>
#include <math.h>
#include <stdint.h>

// Problem constants (B=4, T=4096, D=1024)
#define Bn 4
#define Tn 4096
#define Dn 1024
#define Mn (Bn * Tn)          // 16384

typedef __nv_bfloat16 bf16;

// ---------------- device scratch (alloc-free rule: __device__ globals) -----
__device__ __align__(128) bf16 g_Wh[3][Dn * Dn];     // pre-scaled weights hi
__device__ __align__(128) bf16 g_Wl[3][Dn * Dn];     // lo
__device__ __align__(128) bf16 g_Woh[Dn * Dn];
__device__ __align__(128) bf16 g_Wol[Dn * Dn];
__device__ __align__(128) bf16 g_xh[(size_t)Mn * Dn];   // split of x
__device__ __align__(128) bf16 g_xl[(size_t)Mn * Dn];
__device__ __align__(128) bf16 g_ah[(size_t)Mn * Dn];   // split of rwkv
__device__ __align__(128) bf16 g_al[(size_t)Mn * Dn];
__device__ __align__(128) float g_kvr[3][(size_t)Mn * Dn]; // k,v,r pre-activation
__device__ float g_b[3 * Dn];                            // folded biases

// ---------------- helpers ----------------
__device__ __forceinline__ uint32_t smem_u32(const void* p) {
    uint32_t a;
    asm("{ .reg .u64 t; cvta.to.shared.u64 t, %1; cvt.u32.u64 %0, t; }" : "=r"(a) : "l"(p));
    return a;
}

__device__ __forceinline__ void split2(float v, uint16_t& h, uint16_t& l) {
    bf16 hb = __float2bfloat16_rn(v);
    float r = v - __bfloat162float(hb);
    bf16 lb = __float2bfloat16_rn(r);
    h = *(uint16_t*)&hb;
    l = *(uint16_t*)&lb;
}

__device__ __forceinline__ void cp16(uint32_t saddr, const void* g) {
    asm volatile("cp.async.cg.shared.global [%0], [%1], 16;" :: "r"(saddr), "l"(g));
}
#define CP_COMMIT() asm volatile("cp.async.commit_group;")
#define CP_WAIT1()  asm volatile("cp.async.wait_group 1;")

#define MMA16816(cc, a, b0v, b1v) \
    asm volatile("mma.sync.aligned.m16n8k16.row.col.f32.bf16.bf16.f32 " \
        "{%0,%1,%2,%3}, {%4,%5,%6,%7}, {%8,%9}, {%0,%1,%2,%3};" \
        : "+f"((cc)[0]), "+f"((cc)[1]), "+f"((cc)[2]), "+f"((cc)[3]) \
        : "r"((a)[0]), "r"((a)[1]), "r"((a)[2]), "r"((a)[3]), "r"(b0v), "r"(b1v))

// smem tile geometry: 128 rows x 32 bf16, padded row stride of 40 elems (80B)
#define TSTR 40
#define TILE_E (128 * TSTR)      // elems per tile
#define STAGE_E (4 * TILE_E)     // Ah, Al, Bh, Bl
#define NCH 32                   // K chunks (1024/32)
#define NSTG 3                   // pipeline stages

// A fragment (m16n8k16 row): ldmatrix.x4 -> 4 regs
__device__ __forceinline__ void lda4(uint32_t* r, const bf16* tile, int row0, int k0, int lane) {
    int row = row0 + (lane & 15);
    int col = k0 + ((lane & 16) >> 1);   // lanes 16-31 read k+8 half
    uint32_t a = smem_u32(tile + row * TSTR + col);
    asm volatile("ldmatrix.sync.aligned.m8n8.x4.shared.b16 {%0,%1,%2,%3}, [%4];"
        : "=r"(r[0]), "=r"(r[1]), "=r"(r[2]), "=r"(r[3]) : "r"(a));
}
// B fragments for two adjacent n8 tiles: ldmatrix.x4 -> {n0 reg0, n0 reg1, n1 reg0, n1 reg1}
__device__ __forceinline__ void ldb4(uint32_t* r, const bf16* tile, int row0, int k0, int lane) {
    int row = row0 + (lane & 7) + ((lane & 16) >> 1);
    int col = k0 + (lane & 8);
    uint32_t a = smem_u32(tile + row * TSTR + col);
    asm volatile("ldmatrix.sync.aligned.m8n8.x4.shared.b16 {%0,%1,%2,%3}, [%4];"
        : "=r"(r[0]), "=r"(r[1]), "=r"(r[2]), "=r"(r[3]) : "r"(a));
}

// ---------------- prep kernels ----------------
__global__ void prep_split(const float* __restrict__ src, bf16* __restrict__ dh,
                           bf16* __restrict__ dl, int n4) {
    int i = blockIdx.x * blockDim.x + threadIdx.x;
    if (i >= n4) return;
    float4 v = ((const float4*)src)[i];
    float vv[4] = {v.x, v.y, v.z, v.w};
    uint16_t h[4], l[4];
#pragma unroll
    for (int q = 0; q < 4; q++) split2(vv[q], h[q], l[q]);
    ((uint2*)dh)[i] = make_uint2((uint32_t)h[0] | ((uint32_t)h[1] << 16),
                                 (uint32_t)h[2] | ((uint32_t)h[3] << 16));
    ((uint2*)dl)[i] = make_uint2((uint32_t)l[0] | ((uint32_t)l[1] << 16),
                                 (uint32_t)l[2] | ((uint32_t)l[3] << 16));
}

__global__ void prep_w(const float* __restrict__ Wk, const float* __restrict__ Wv,
                       const float* __restrict__ Wr, const float* __restrict__ tmk,
                       const float* __restrict__ tmv, const float* __restrict__ tmr) {
    int idx = blockIdx.x * blockDim.x + threadIdx.x;
    if (idx >= Dn * Dn / 4) return;
    int basei = idx * 4;
    int d = basei & (Dn - 1);
    const float* Ws[3] = {Wk, Wv, Wr};
    const float* Tm[3] = {tmk, tmv, tmr};
#pragma unroll
    for (int i = 0; i < 3; i++) {
        float4 w = *(const float4*)&Ws[i][basei];
        float4 mm = *(const float4*)&Tm[i][d];
        float vv[4] = {w.x * mm.x, w.y * mm.y, w.z * mm.z, w.w * mm.w};
        uint16_t h[4], l[4];
#pragma unroll
        for (int q = 0; q < 4; q++) split2(vv[q], h[q], l[q]);
        *(uint2*)&g_Wh[i][basei] = make_uint2((uint32_t)h[0] | ((uint32_t)h[1] << 16),
                                              (uint32_t)h[2] | ((uint32_t)h[3] << 16));
        *(uint2*)&g_Wl[i][basei] = make_uint2((uint32_t)l[0] | ((uint32_t)l[1] << 16),
                                              (uint32_t)l[2] | ((uint32_t)l[3] << 16));
    }
}

__global__ void prep_bias(const float* __restrict__ Wk, const float* __restrict__ Wv,
                          const float* __restrict__ Wr, const float* __restrict__ lx,
                          const float* __restrict__ tmk, const float* __restrict__ tmv,
                          const float* __restrict__ tmr) {
    __shared__ float red[256];
    int e = blockIdx.x;
    int t = threadIdx.x;
    const float* Ws[3] = {Wk, Wv, Wr};
    const float* tms[3] = {tmk, tmv, tmr};
#pragma unroll
    for (int i = 0; i < 3; i++) {
        float s = 0.f;
        for (int d = t; d < Dn; d += 256)
            s += Ws[i][(size_t)e * Dn + d] * lx[d] * (1.f - tms[i][d]);
        red[t] = s;
        __syncthreads();
        for (int off = 128; off > 0; off >>= 1) {
            if (t < off) red[t] += red[t + off];
            __syncthreads();
        }
        if (t == 0) g_b[i * Dn + e] = red[0];
        __syncthreads();
    }
}

// ---------------- generic bf16x3 GEMM: C[m][n] = sum_k A[m][k] * B[n][k] ----
// mode 0: A = x split, B = W[z] split, C = g_kvr[z]   (grid.z = 3)
// mode 1: A = rwkv split, B = Wo split, C = outp      (grid.z = 1)
__global__ __launch_bounds__(256, 1)
void gemm_bf16x3(int mode, float* __restrict__ outp) {
    extern __shared__ bf16 sm[];
    const int t = threadIdx.x;
    const int lane = t & 31, wid = t >> 5;
    const int e0 = blockIdx.x * 128, m0 = blockIdx.y * 128;
    const int z = blockIdx.z;

    const bf16 *Ah, *Al, *Bh, *Bl;
    float* C;
    if (mode == 0) { Ah = g_xh; Al = g_xl; Bh = g_Wh[z]; Bl = g_Wl[z]; C = g_kvr[z]; }
    else           { Ah = g_ah; Al = g_al; Bh = g_Woh;   Bl = g_Wol;   C = outp; }

    uint32_t sbase = smem_u32(sm);

    auto stage_load = [&](int ch, int stg) {
        uint32_t s0 = sbase + stg * STAGE_E * 2;
        int kcol = ch * 32;
#pragma unroll
        for (int i = 0; i < 2; i++) {
            int idx = t + i * 256;
            int row = idx >> 2, q = idx & 3;
            uint32_t soff = (uint32_t)(row * TSTR + q * 8) * 2;
            size_t goffA = (size_t)(m0 + row) * Dn + kcol + q * 8;
            size_t goffB = (size_t)(e0 + row) * Dn + kcol + q * 8;
            cp16(s0 + soff,                Ah + goffA);
            cp16(s0 + TILE_E * 2 + soff,   Al + goffA);
            cp16(s0 + TILE_E * 4 + soff,   Bh + goffB);
            cp16(s0 + TILE_E * 6 + soff,   Bl + goffB);
        }
    };

    float c[4][4][4];
#pragma unroll
    for (int i = 0; i < 4; i++)
#pragma unroll
        for (int j = 0; j < 4; j++)
#pragma unroll
            for (int q = 0; q < 4; q++) c[i][j][q] = 0.f;

    // prologue: fill stages 0..NSTG-2
    stage_load(0, 0); CP_COMMIT();
    stage_load(1, 1); CP_COMMIT();

    const int mw = (wid >> 2) * 64;   // warp m offset within the 128-tile
    const int nw = (wid & 3) * 32;    // warp n offset

    for (int ch = 0; ch < NCH; ch++) {
        // guarantee stage ch%NSTG is resident (at most 1 newer group in flight)
        CP_WAIT1();
        // one barrier: orders previous compute (reads of buffer (ch+2)%3)
        // before this iteration's load into that same buffer
        __syncthreads();
        if (ch + NSTG - 1 < NCH) stage_load(ch + NSTG - 1, (ch + NSTG - 1) % NSTG);
        CP_COMMIT();

        const bf16* st  = sm + (ch % NSTG) * STAGE_E;
        const bf16* tAh = st;
        const bf16* tAl = st + TILE_E;
        const bf16* tBh = st + 2 * TILE_E;
        const bf16* tBl = st + 3 * TILE_E;
#pragma unroll
        for (int s = 0; s < 2; s++) {
            int k0 = s * 16;
            uint32_t ah[4][4], al[4][4], bh[2][4], bl[2][4];
#pragma unroll
            for (int i = 0; i < 4; i++) {
                lda4(ah[i], tAh, mw + i * 16, k0, lane);
                lda4(al[i], tAl, mw + i * 16, k0, lane);
            }
#pragma unroll
            for (int jj = 0; jj < 2; jj++) {
                ldb4(bh[jj], tBh, nw + jj * 16, k0, lane);
                ldb4(bl[jj], tBl, nw + jj * 16, k0, lane);
            }
#pragma unroll
            for (int i = 0; i < 4; i++)
#pragma unroll
                for (int j = 0; j < 4; j++) {
                    uint32_t hb0 = bh[j >> 1][(j & 1) * 2], hb1 = bh[j >> 1][(j & 1) * 2 + 1];
                    uint32_t lb0 = bl[j >> 1][(j & 1) * 2], lb1 = bl[j >> 1][(j & 1) * 2 + 1];
                    MMA16816(c[i][j], ah[i], hb0, hb1);   // hi * hi
                    MMA16816(c[i][j], al[i], hb0, hb1);   // lo * hi
                    MMA16816(c[i][j], ah[i], lb0, lb1);   // hi * lo
                }
        }
    }

    // epilogue: write fp32 C
#pragma unroll
    for (int i = 0; i < 4; i++) {
        int mrow = m0 + mw + i * 16 + (lane >> 2);
#pragma unroll
        for (int j = 0; j < 4; j++) {
            int ncol = e0 + nw + j * 8 + (lane & 3) * 2;
            *(float2*)&C[(size_t)mrow * Dn + ncol] = make_float2(c[i][j][0], c[i][j][1]);
            *(float2*)&C[(size_t)(mrow + 8) * Dn + ncol] = make_float2(c[i][j][2], c[i][j][3]);
        }
    }
}

// ---------------- WKV elementwise epilogue ----------------
__global__ void wkv_ep(const float* __restrict__ tf, const float* __restrict__ td,
                       const float* __restrict__ lnum, const float* __restrict__ lden,
                       float* __restrict__ out_num, float* __restrict__ out_den) {
    int i = blockIdx.x * blockDim.x + threadIdx.x;     // over Mn*Dn/4
    if (i >= Mn * Dn / 4) return;
    int m = i >> 8;                 // Dn/4 = 256 float4 per row
    int e = (i & 255) * 4;
    size_t off = (size_t)m * Dn + e;
    float4 k4 = *(const float4*)&g_kvr[0][off];
    float4 v4 = *(const float4*)&g_kvr[1][off];
    float4 r4 = *(const float4*)&g_kvr[2][off];
    float kk[4] = {k4.x, k4.y, k4.z, k4.w};
    float vv[4] = {v4.x, v4.y, v4.z, v4.w};
    float rr[4] = {r4.x, r4.y, r4.z, r4.w};
    const bool last = ((m & (Tn - 1)) == (Tn - 1));
    const int bidx = m >> 12;
    uint16_t h[4], l[4];
#pragma unroll
    for (int q = 0; q < 4; q++) {
        int eq = e + q;
        float kv = kk[q] + g_b[eq];
        float vvq = vv[q] + g_b[Dn + eq];
        float rv = rr[q] + g_b[2 * Dn + eq];
        float efk = expf(tf[eq] + kv);
        float wkv = (lnum[eq] + efk * vvq) / (lden[eq] + efk);
        float val = wkv / (1.f + expf(-rv));
        split2(val, h[q], l[q]);
        if (last) {
            float ek = expf(kv);
            float dec = expf(-expf(td[eq]));
            out_num[bidx * Dn + eq] = dec * lnum[eq] + ek * vvq;
            out_den[bidx * Dn + eq] = dec * lden[eq] + ek;
        }
    }
    ((uint2*)g_ah)[i] = make_uint2((uint32_t)h[0] | ((uint32_t)h[1] << 16),
                                   (uint32_t)h[2] | ((uint32_t)h[3] << 16));
    ((uint2*)g_al)[i] = make_uint2((uint32_t)l[0] | ((uint32_t)l[1] << 16),
                                   (uint32_t)l[2] | ((uint32_t)l[3] << 16));
}

// ---------------- tail ----------------
__global__ void tail_xlast(const float* __restrict__ x, float* __restrict__ out_x) {
    int i = blockIdx.x * blockDim.x + threadIdx.x;
    if (i < Bn * Dn) {
        int b = i / Dn;
        int d = i & (Dn - 1);
        out_x[i] = x[((size_t)b * Tn + (Tn - 1)) * Dn + d];
    }
}

// ---------------- launch ----------------
extern "C" void kernel_launch(void* const* d_in, const int* in_sizes, int n_in,
                              void* d_out, int out_size) {
    const float* x        = (const float*)d_in[0];
    const float* last_x   = (const float*)d_in[1];
    const float* last_num = (const float*)d_in[2];
    const float* last_den = (const float*)d_in[3];
    const float* td  = (const float*)d_in[4];
    const float* tf  = (const float*)d_in[5];
    const float* tmk = (const float*)d_in[6];
    const float* tmv = (const float*)d_in[7];
    const float* tmr = (const float*)d_in[8];
    const float* Wk  = (const float*)d_in[9];
    const float* Wv  = (const float*)d_in[10];
    const float* Wr  = (const float*)d_in[11];
    const float* Wo  = (const float*)d_in[12];

    float* out     = (float*)d_out;
    float* out_x   = out + (size_t)Mn * Dn;
    float* out_num = out_x + Bn * Dn;
    float* out_den = out_num + Bn * Dn;

    const int GEMM_SMEM = NSTG * STAGE_E * 2;   // 122880 bytes
    cudaFuncSetAttribute(gemm_bf16x3, cudaFuncAttributeMaxDynamicSharedMemorySize, GEMM_SMEM);

    bf16 *p_xh, *p_xl, *p_woh, *p_wol;
    cudaGetSymbolAddress((void**)&p_xh, g_xh);
    cudaGetSymbolAddress((void**)&p_xl, g_xl);
    cudaGetSymbolAddress((void**)&p_woh, g_Woh);
    cudaGetSymbolAddress((void**)&p_wol, g_Wol);

    // prep
    prep_w<<<(Dn * Dn / 4 + 255) / 256, 256>>>(Wk, Wv, Wr, tmk, tmv, tmr);
    prep_split<<<(Dn * Dn / 4 + 255) / 256, 256>>>(Wo, p_woh, p_wol, Dn * Dn / 4);
    prep_split<<<(Mn * Dn / 4 + 255) / 256, 256>>>(x, p_xh, p_xl, Mn * Dn / 4);
    prep_bias<<<Dn, 256>>>(Wk, Wv, Wr, last_x, tmk, tmv, tmr);

    // k, v, r GEMMs (z = 0..2)
    dim3 grid_kvr(Dn / 128, Mn / 128, 3);
    gemm_bf16x3<<<grid_kvr, 256, GEMM_SMEM>>>(0, nullptr);

    // WKV elementwise + rwkv split
    wkv_ep<<<(Mn * Dn / 4 + 255) / 256, 256>>>(tf, td, last_num, last_den, out_num, out_den);

    // output GEMM
    dim3 grid_out(Dn / 128, Mn / 128, 1);
    gemm_bf16x3<<<grid_out, 256, GEMM_SMEM>>>(1, out);

    tail_xlast<<<(Bn * Dn + 255) / 256, 256>>>(x, out_x);
}

// round 9
// speedup vs baseline: 1.0846x; 1.0846x over previous
#include <cuda_runtime.h>
#include <cuda_bf16.h>
#include <math.h>
#include <stdint.h>

// Problem constants (B=4, T=4096, D=1024)
#define Bn 4
#define Tn 4096
#define Dn 1024
#define Mn (Bn * Tn)          // 16384

typedef __nv_bfloat16 bf16;

// ---------------- device scratch (alloc-free rule: __device__ globals) -----
__device__ __align__(128) bf16 g_Wh[3][Dn * Dn];     // pre-scaled weights hi
__device__ __align__(128) bf16 g_Wl[3][Dn * Dn];     // lo
__device__ __align__(128) bf16 g_Woh[Dn * Dn];
__device__ __align__(128) bf16 g_Wol[Dn * Dn];
__device__ __align__(128) bf16 g_xh[(size_t)Mn * Dn];   // split of x
__device__ __align__(128) bf16 g_xl[(size_t)Mn * Dn];
__device__ __align__(128) bf16 g_ah[(size_t)Mn * Dn];   // split of rwkv
__device__ __align__(128) bf16 g_al[(size_t)Mn * Dn];
__device__ float g_b[3 * Dn];                            // folded biases

// ---------------- helpers ----------------
__device__ __forceinline__ uint32_t smem_u32(const void* p) {
    uint32_t a;
    asm("{ .reg .u64 t; cvta.to.shared.u64 t, %1; cvt.u32.u64 %0, t; }" : "=r"(a) : "l"(p));
    return a;
}

__device__ __forceinline__ void split2(float v, uint16_t& h, uint16_t& l) {
    bf16 hb = __float2bfloat16_rn(v);
    float r = v - __bfloat162float(hb);
    bf16 lb = __float2bfloat16_rn(r);
    h = *(uint16_t*)&hb;
    l = *(uint16_t*)&lb;
}

__device__ __forceinline__ void cp16(uint32_t saddr, const void* g) {
    asm volatile("cp.async.cg.shared.global [%0], [%1], 16;" :: "r"(saddr), "l"(g));
}
#define CP_COMMIT() asm volatile("cp.async.commit_group;")
#define CP_WAIT1()  asm volatile("cp.async.wait_group 1;")

#define MMA16816(cc, a, b0v, b1v) \
    asm volatile("mma.sync.aligned.m16n8k16.row.col.f32.bf16.bf16.f32 " \
        "{%0,%1,%2,%3}, {%4,%5,%6,%7}, {%8,%9}, {%0,%1,%2,%3};" \
        : "+f"((cc)[0]), "+f"((cc)[1]), "+f"((cc)[2]), "+f"((cc)[3]) \
        : "r"((a)[0]), "r"((a)[1]), "r"((a)[2]), "r"((a)[3]), "r"(b0v), "r"(b1v))

// smem tile geometry: rows x 32 bf16, padded row stride of 40 elems (80B)
#define TSTR 40
#define NCH 32                   // K chunks (1024/32)

// out-GEMM tiles (128x128): as in R6
#define TILE_E (128 * TSTR)
#define STAGE_E (4 * TILE_E)     // Ah, Al, Bh, Bl

// fused kvr tiles (128 m x 64 n)
#define FA_E (128 * TSTR)        // A tile elems (128 rows)
#define FB_E (64 * TSTR)         // B tile elems (64 rows)
#define FSTAGE_E (2 * FA_E + 6 * FB_E)   // Ah, Al, 3x(Bh, Bl) = 25600 elems

// A fragment (m16n8k16 row): ldmatrix.x4 -> 4 regs
__device__ __forceinline__ void lda4(uint32_t* r, const bf16* tile, int row0, int k0, int lane) {
    int row = row0 + (lane & 15);
    int col = k0 + ((lane & 16) >> 1);   // lanes 16-31 read k+8 half
    uint32_t a = smem_u32(tile + row * TSTR + col);
    asm volatile("ldmatrix.sync.aligned.m8n8.x4.shared.b16 {%0,%1,%2,%3}, [%4];"
        : "=r"(r[0]), "=r"(r[1]), "=r"(r[2]), "=r"(r[3]) : "r"(a));
}
// B fragments for two adjacent n8 tiles: ldmatrix.x4
__device__ __forceinline__ void ldb4(uint32_t* r, const bf16* tile, int row0, int k0, int lane) {
    int row = row0 + (lane & 7) + ((lane & 16) >> 1);
    int col = k0 + (lane & 8);
    uint32_t a = smem_u32(tile + row * TSTR + col);
    asm volatile("ldmatrix.sync.aligned.m8n8.x4.shared.b16 {%0,%1,%2,%3}, [%4];"
        : "=r"(r[0]), "=r"(r[1]), "=r"(r[2]), "=r"(r[3]) : "r"(a));
}

// ---------------- prep kernels ----------------
__global__ void prep_split(const float* __restrict__ src, bf16* __restrict__ dh,
                           bf16* __restrict__ dl, int n4) {
    int i = blockIdx.x * blockDim.x + threadIdx.x;
    if (i >= n4) return;
    float4 v = ((const float4*)src)[i];
    float vv[4] = {v.x, v.y, v.z, v.w};
    uint16_t h[4], l[4];
#pragma unroll
    for (int q = 0; q < 4; q++) split2(vv[q], h[q], l[q]);
    ((uint2*)dh)[i] = make_uint2((uint32_t)h[0] | ((uint32_t)h[1] << 16),
                                 (uint32_t)h[2] | ((uint32_t)h[3] << 16));
    ((uint2*)dl)[i] = make_uint2((uint32_t)l[0] | ((uint32_t)l[1] << 16),
                                 (uint32_t)l[2] | ((uint32_t)l[3] << 16));
}

__global__ void prep_w(const float* __restrict__ Wk, const float* __restrict__ Wv,
                       const float* __restrict__ Wr, const float* __restrict__ tmk,
                       const float* __restrict__ tmv, const float* __restrict__ tmr) {
    int idx = blockIdx.x * blockDim.x + threadIdx.x;
    if (idx >= Dn * Dn / 4) return;
    int basei = idx * 4;
    int d = basei & (Dn - 1);
    const float* Ws[3] = {Wk, Wv, Wr};
    const float* Tm[3] = {tmk, tmv, tmr};
#pragma unroll
    for (int i = 0; i < 3; i++) {
        float4 w = *(const float4*)&Ws[i][basei];
        float4 mm = *(const float4*)&Tm[i][d];
        float vv[4] = {w.x * mm.x, w.y * mm.y, w.z * mm.z, w.w * mm.w};
        uint16_t h[4], l[4];
#pragma unroll
        for (int q = 0; q < 4; q++) split2(vv[q], h[q], l[q]);
        *(uint2*)&g_Wh[i][basei] = make_uint2((uint32_t)h[0] | ((uint32_t)h[1] << 16),
                                              (uint32_t)h[2] | ((uint32_t)h[3] << 16));
        *(uint2*)&g_Wl[i][basei] = make_uint2((uint32_t)l[0] | ((uint32_t)l[1] << 16),
                                              (uint32_t)l[2] | ((uint32_t)l[3] << 16));
    }
}

__global__ void prep_bias(const float* __restrict__ Wk, const float* __restrict__ Wv,
                          const float* __restrict__ Wr, const float* __restrict__ lx,
                          const float* __restrict__ tmk, const float* __restrict__ tmv,
                          const float* __restrict__ tmr) {
    __shared__ float red[256];
    int e = blockIdx.x;
    int t = threadIdx.x;
    const float* Ws[3] = {Wk, Wv, Wr};
    const float* tms[3] = {tmk, tmv, tmr};
#pragma unroll
    for (int i = 0; i < 3; i++) {
        float s = 0.f;
        for (int d = t; d < Dn; d += 256)
            s += Ws[i][(size_t)e * Dn + d] * lx[d] * (1.f - tms[i][d]);
        red[t] = s;
        __syncthreads();
        for (int off = 128; off > 0; off >>= 1) {
            if (t < off) red[t] += red[t + off];
            __syncthreads();
        }
        if (t == 0) g_b[i * Dn + e] = red[0];
        __syncthreads();
    }
}

// ---------------- fused k/v/r GEMM + WKV epilogue ----------------
// CTA tile: 128 m x 64 n. 8 warps, each owning 32x32 of ALL THREE outputs.
// Epilogue computes rwkv (bf16 split -> g_ah/g_al) + last-token num/den.
__global__ __launch_bounds__(256, 1)
void gemm_kvr_fused(const float* __restrict__ tf, const float* __restrict__ td,
                    const float* __restrict__ lnum, const float* __restrict__ lden,
                    float* __restrict__ out_num, float* __restrict__ out_den) {
    extern __shared__ bf16 sm[];
    const int t = threadIdx.x;
    const int lane = t & 31, wid = t >> 5;
    const int e0 = blockIdx.x * 64, m0 = blockIdx.y * 128;

    uint32_t sbase = smem_u32(sm);

    auto stage_load = [&](int ch, int stg) {
        uint32_t s0 = sbase + stg * FSTAGE_E * 2;
        int kcol = ch * 32;
        // A tiles (128 rows): 512 thread-ops per tile -> 2 iters
#pragma unroll
        for (int i = 0; i < 2; i++) {
            int idx = t + i * 256;
            int row = idx >> 2, q = idx & 3;
            uint32_t soff = (uint32_t)(row * TSTR + q * 8) * 2;
            size_t g = (size_t)(m0 + row) * Dn + kcol + q * 8;
            cp16(s0 + soff,             g_xh + g);
            cp16(s0 + FA_E * 2 + soff,  g_xl + g);
        }
        // B tiles (64 rows): 256 thread-ops per tile -> 1 iter, 3 matrices
        {
            int row = t >> 2, q = t & 3;
            uint32_t soff = (uint32_t)(row * TSTR + q * 8) * 2;
            size_t g = (size_t)(e0 + row) * Dn + kcol + q * 8;
#pragma unroll
            for (int z = 0; z < 3; z++) {
                cp16(s0 + (2 * FA_E + (2 * z + 0) * FB_E) * 2 + soff, &g_Wh[z][0] + g);
                cp16(s0 + (2 * FA_E + (2 * z + 1) * FB_E) * 2 + soff, &g_Wl[z][0] + g);
            }
        }
    };

    float c[3][2][4][4];
#pragma unroll
    for (int z = 0; z < 3; z++)
#pragma unroll
        for (int i = 0; i < 2; i++)
#pragma unroll
            for (int j = 0; j < 4; j++)
#pragma unroll
                for (int q = 0; q < 4; q++) c[z][i][j][q] = 0.f;

    stage_load(0, 0); CP_COMMIT();
    stage_load(1, 1); CP_COMMIT();

    const int mw = (wid >> 1) * 32;   // warp m offset (0..96)
    const int nw = (wid & 1) * 32;    // warp n offset (0/32)

    for (int ch = 0; ch < NCH; ch++) {
        CP_WAIT1();
        __syncthreads();
        const bf16* st  = sm + (ch & 1) * FSTAGE_E;
        const bf16* tAh = st;
        const bf16* tAl = st + FA_E;
#pragma unroll
        for (int s = 0; s < 2; s++) {
            int k0 = s * 16;
            uint32_t ah[2][4], al[2][4];
#pragma unroll
            for (int i = 0; i < 2; i++) {
                lda4(ah[i], tAh, mw + i * 16, k0, lane);
                lda4(al[i], tAl, mw + i * 16, k0, lane);
            }
#pragma unroll
            for (int z = 0; z < 3; z++) {
                const bf16* tBh = st + 2 * FA_E + (2 * z + 0) * FB_E;
                const bf16* tBl = st + 2 * FA_E + (2 * z + 1) * FB_E;
                uint32_t bh[2][4], bl[2][4];
                ldb4(bh[0], tBh, nw, k0, lane);
                ldb4(bh[1], tBh, nw + 16, k0, lane);
                ldb4(bl[0], tBl, nw, k0, lane);
                ldb4(bl[1], tBl, nw + 16, k0, lane);
#pragma unroll
                for (int i = 0; i < 2; i++)
#pragma unroll
                    for (int j = 0; j < 4; j++) {
                        uint32_t hb0 = bh[j >> 1][(j & 1) * 2], hb1 = bh[j >> 1][(j & 1) * 2 + 1];
                        uint32_t lb0 = bl[j >> 1][(j & 1) * 2], lb1 = bl[j >> 1][(j & 1) * 2 + 1];
                        MMA16816(c[z][i][j], ah[i], hb0, hb1);   // hi*hi
                        MMA16816(c[z][i][j], al[i], hb0, hb1);   // lo*hi
                        MMA16816(c[z][i][j], ah[i], lb0, lb1);   // hi*lo
                    }
            }
        }
        __syncthreads();
        if (ch + 2 < NCH) stage_load(ch + 2, ch & 1);
        CP_COMMIT();
    }

    // ---- fused WKV epilogue (each warp owns all of k,v,r for its 32x32) ----
#pragma unroll
    for (int j = 0; j < 4; j++) {
        int e = e0 + nw + j * 8 + (lane & 3) * 2;   // two consecutive e: e, e+1
        float tf0 = tf[e],         tf1 = tf[e + 1];
        float bk0 = g_b[e],        bk1 = g_b[e + 1];
        float bv0 = g_b[Dn + e],   bv1 = g_b[Dn + e + 1];
        float br0 = g_b[2*Dn + e], br1 = g_b[2*Dn + e + 1];
        float ln0 = lnum[e],       ln1 = lnum[e + 1];
        float ld0 = lden[e],       ld1 = lden[e + 1];
#pragma unroll
        for (int i = 0; i < 2; i++) {
#pragma unroll
            for (int half = 0; half < 2; half++) {   // half 0: rows r, half 1: r+8
                int m = m0 + mw + i * 16 + (lane >> 2) + half * 8;
                int q0 = half * 2, q1 = half * 2 + 1;
                float kv0 = c[0][i][j][q0] + bk0, kv1 = c[0][i][j][q1] + bk1;
                float vv0 = c[1][i][j][q0] + bv0, vv1 = c[1][i][j][q1] + bv1;
                float rv0 = c[2][i][j][q0] + br0, rv1 = c[2][i][j][q1] + br1;
                float efk0 = expf(tf0 + kv0), efk1 = expf(tf1 + kv1);
                float wkv0 = (ln0 + efk0 * vv0) / (ld0 + efk0);
                float wkv1 = (ln1 + efk1 * vv1) / (ld1 + efk1);
                float val0 = wkv0 / (1.f + expf(-rv0));
                float val1 = wkv1 / (1.f + expf(-rv1));
                uint16_t h0, l0, h1, l1;
                split2(val0, h0, l0);
                split2(val1, h1, l1);
                size_t off = ((size_t)m * Dn + e) >> 1;   // u32 index
                ((uint32_t*)g_ah)[off] = (uint32_t)h0 | ((uint32_t)h1 << 16);
                ((uint32_t*)g_al)[off] = (uint32_t)l0 | ((uint32_t)l1 << 16);
                if ((m & (Tn - 1)) == (Tn - 1)) {
                    int bidx = m >> 12;
                    float ek0 = expf(kv0), ek1 = expf(kv1);
                    float dc0 = expf(-expf(td[e])), dc1 = expf(-expf(td[e + 1]));
                    out_num[bidx * Dn + e]     = dc0 * ln0 + ek0 * vv0;
                    out_num[bidx * Dn + e + 1] = dc1 * ln1 + ek1 * vv1;
                    out_den[bidx * Dn + e]     = dc0 * ld0 + ek0;
                    out_den[bidx * Dn + e + 1] = dc1 * ld1 + ek1;
                }
            }
        }
    }
}

// ---------------- out GEMM: out = rwkv @ Wo^T (R6 structure, 128x128) -----
__global__ __launch_bounds__(256, 1)
void gemm_out_mma(float* __restrict__ outp) {
    extern __shared__ bf16 sm[];
    const int t = threadIdx.x;
    const int lane = t & 31, wid = t >> 5;
    const int e0 = blockIdx.x * 128, m0 = blockIdx.y * 128;

    uint32_t sbase = smem_u32(sm);

    auto stage_load = [&](int ch, int stg) {
        uint32_t s0 = sbase + stg * STAGE_E * 2;
        int kcol = ch * 32;
#pragma unroll
        for (int i = 0; i < 2; i++) {
            int idx = t + i * 256;
            int row = idx >> 2, q = idx & 3;
            uint32_t soff = (uint32_t)(row * TSTR + q * 8) * 2;
            size_t goffA = (size_t)(m0 + row) * Dn + kcol + q * 8;
            size_t goffB = (size_t)(e0 + row) * Dn + kcol + q * 8;
            cp16(s0 + soff,               g_ah + goffA);
            cp16(s0 + TILE_E * 2 + soff,  g_al + goffA);
            cp16(s0 + TILE_E * 4 + soff,  g_Woh + goffB);
            cp16(s0 + TILE_E * 6 + soff,  g_Wol + goffB);
        }
    };

    float c[4][4][4];
#pragma unroll
    for (int i = 0; i < 4; i++)
#pragma unroll
        for (int j = 0; j < 4; j++)
#pragma unroll
            for (int q = 0; q < 4; q++) c[i][j][q] = 0.f;

    stage_load(0, 0); CP_COMMIT();
    stage_load(1, 1); CP_COMMIT();

    const int mw = (wid >> 2) * 64;
    const int nw = (wid & 3) * 32;

    for (int ch = 0; ch < NCH; ch++) {
        CP_WAIT1();
        __syncthreads();
        const bf16* st  = sm + (ch & 1) * STAGE_E;
        const bf16* tAh = st;
        const bf16* tAl = st + TILE_E;
        const bf16* tBh = st + 2 * TILE_E;
        const bf16* tBl = st + 3 * TILE_E;
#pragma unroll
        for (int s = 0; s < 2; s++) {
            int k0 = s * 16;
            uint32_t ah[4][4], al[4][4], bh[2][4], bl[2][4];
#pragma unroll
            for (int i = 0; i < 4; i++) {
                lda4(ah[i], tAh, mw + i * 16, k0, lane);
                lda4(al[i], tAl, mw + i * 16, k0, lane);
            }
#pragma unroll
            for (int jj = 0; jj < 2; jj++) {
                ldb4(bh[jj], tBh, nw + jj * 16, k0, lane);
                ldb4(bl[jj], tBl, nw + jj * 16, k0, lane);
            }
#pragma unroll
            for (int i = 0; i < 4; i++)
#pragma unroll
                for (int j = 0; j < 4; j++) {
                    uint32_t hb0 = bh[j >> 1][(j & 1) * 2], hb1 = bh[j >> 1][(j & 1) * 2 + 1];
                    uint32_t lb0 = bl[j >> 1][(j & 1) * 2], lb1 = bl[j >> 1][(j & 1) * 2 + 1];
                    MMA16816(c[i][j], ah[i], hb0, hb1);
                    MMA16816(c[i][j], al[i], hb0, hb1);
                    MMA16816(c[i][j], ah[i], lb0, lb1);
                }
        }
        __syncthreads();
        if (ch + 2 < NCH) stage_load(ch + 2, ch & 1);
        CP_COMMIT();
    }

#pragma unroll
    for (int i = 0; i < 4; i++) {
        int mrow = m0 + mw + i * 16 + (lane >> 2);
#pragma unroll
        for (int j = 0; j < 4; j++) {
            int ncol = e0 + nw + j * 8 + (lane & 3) * 2;
            *(float2*)&outp[(size_t)mrow * Dn + ncol] = make_float2(c[i][j][0], c[i][j][1]);
            *(float2*)&outp[(size_t)(mrow + 8) * Dn + ncol] = make_float2(c[i][j][2], c[i][j][3]);
        }
    }
}

// ---------------- tail ----------------
__global__ void tail_xlast(const float* __restrict__ x, float* __restrict__ out_x) {
    int i = blockIdx.x * blockDim.x + threadIdx.x;
    if (i < Bn * Dn) {
        int b = i / Dn;
        int d = i & (Dn - 1);
        out_x[i] = x[((size_t)b * Tn + (Tn - 1)) * Dn + d];
    }
}

// ---------------- launch ----------------
extern "C" void kernel_launch(void* const* d_in, const int* in_sizes, int n_in,
                              void* d_out, int out_size) {
    const float* x        = (const float*)d_in[0];
    const float* last_x   = (const float*)d_in[1];
    const float* last_num = (const float*)d_in[2];
    const float* last_den = (const float*)d_in[3];
    const float* td  = (const float*)d_in[4];
    const float* tf  = (const float*)d_in[5];
    const float* tmk = (const float*)d_in[6];
    const float* tmv = (const float*)d_in[7];
    const float* tmr = (const float*)d_in[8];
    const float* Wk  = (const float*)d_in[9];
    const float* Wv  = (const float*)d_in[10];
    const float* Wr  = (const float*)d_in[11];
    const float* Wo  = (const float*)d_in[12];

    float* out     = (float*)d_out;
    float* out_x   = out + (size_t)Mn * Dn;
    float* out_num = out_x + Bn * Dn;
    float* out_den = out_num + Bn * Dn;

    const int KVR_SMEM = 2 * FSTAGE_E * 2;   // 102400 bytes
    const int OUT_SMEM = 2 * STAGE_E * 2;    // 81920 bytes
    cudaFuncSetAttribute(gemm_kvr_fused, cudaFuncAttributeMaxDynamicSharedMemorySize, KVR_SMEM);
    cudaFuncSetAttribute(gemm_out_mma, cudaFuncAttributeMaxDynamicSharedMemorySize, OUT_SMEM);

    bf16 *p_xh, *p_xl, *p_woh, *p_wol;
    cudaGetSymbolAddress((void**)&p_xh, g_xh);
    cudaGetSymbolAddress((void**)&p_xl, g_xl);
    cudaGetSymbolAddress((void**)&p_woh, g_Woh);
    cudaGetSymbolAddress((void**)&p_wol, g_Wol);

    // prep
    prep_w<<<(Dn * Dn / 4 + 255) / 256, 256>>>(Wk, Wv, Wr, tmk, tmv, tmr);
    prep_split<<<(Dn * Dn / 4 + 255) / 256, 256>>>(Wo, p_woh, p_wol, Dn * Dn / 4);
    prep_split<<<(Mn * Dn / 4 + 255) / 256, 256>>>(x, p_xh, p_xl, Mn * Dn / 4);
    prep_bias<<<Dn, 256>>>(Wk, Wv, Wr, last_x, tmk, tmv, tmr);

    // fused k/v/r GEMM + WKV epilogue
    dim3 grid_kvr(Dn / 64, Mn / 128);   // (16, 128) = 2048 CTAs
    gemm_kvr_fused<<<grid_kvr, 256, KVR_SMEM>>>(tf, td, last_num, last_den, out_num, out_den);

    // output GEMM
    dim3 grid_out(Dn / 128, Mn / 128);  // (8, 128) = 1024 CTAs
    gemm_out_mma<<<grid_out, 256, OUT_SMEM>>>(out);

    tail_xlast<<<(Bn * Dn + 255) / 256, 256>>>(x, out_x);
}

// round 10
// speedup vs baseline: 1.5802x; 1.4569x over previous
#include <cuda_runtime.h>
#include <cuda_fp16.h>
#include <math.h>
#include <stdint.h>

// Problem constants (B=4, T=4096, D=1024)
#define Bn 4
#define Tn 4096
#define Dn 1024
#define Mn (Bn * Tn)          // 16384

typedef __half f16;

// ---------------- device scratch (alloc-free rule: __device__ globals) -----
__device__ __align__(128) f16 g_Wh[3][Dn * Dn];      // pre-scaled weights, fp16 (hi only)
__device__ __align__(128) f16 g_Woh[Dn * Dn];        // Wo fp16 (hi only)
__device__ __align__(128) f16 g_xh[(size_t)Mn * Dn]; // x split hi
__device__ __align__(128) f16 g_xl[(size_t)Mn * Dn]; // x split lo
__device__ __align__(128) f16 g_ah[(size_t)Mn * Dn]; // rwkv split hi
__device__ __align__(128) f16 g_al[(size_t)Mn * Dn]; // rwkv split lo
__device__ float g_b[3 * Dn];                        // folded biases

// ---------------- helpers ----------------
__device__ __forceinline__ uint32_t smem_u32(const void* p) {
    uint32_t a;
    asm("{ .reg .u64 t; cvta.to.shared.u64 t, %1; cvt.u32.u64 %0, t; }" : "=r"(a) : "l"(p));
    return a;
}

// fp32 -> fp16 hi/lo split (hi+lo captures ~22 mantissa bits)
__device__ __forceinline__ void split2h(float v, uint16_t& h, uint16_t& l) {
    f16 hb = __float2half_rn(v);
    float r = v - __half2float(hb);
    f16 lb = __float2half_rn(r);
    h = *(uint16_t*)&hb;
    l = *(uint16_t*)&lb;
}

__device__ __forceinline__ void cp16(uint32_t saddr, const void* g) {
    asm volatile("cp.async.cg.shared.global [%0], [%1], 16;" :: "r"(saddr), "l"(g));
}
#define CP_COMMIT() asm volatile("cp.async.commit_group;")
#define CP_WAIT1()  asm volatile("cp.async.wait_group 1;")

#define MMA16816(cc, a, b0v, b1v) \
    asm volatile("mma.sync.aligned.m16n8k16.row.col.f32.f16.f16.f32 " \
        "{%0,%1,%2,%3}, {%4,%5,%6,%7}, {%8,%9}, {%0,%1,%2,%3};" \
        : "+f"((cc)[0]), "+f"((cc)[1]), "+f"((cc)[2]), "+f"((cc)[3]) \
        : "r"((a)[0]), "r"((a)[1]), "r"((a)[2]), "r"((a)[3]), "r"(b0v), "r"(b1v))

// smem tile geometry: rows x 32 halves, padded row stride of 40 elems (80B)
#define TSTR 40
#define NCH 32                   // K chunks (1024/32)

// out-GEMM tiles (128x128): Ah, Al, Bh
#define TILE_E (128 * TSTR)
#define OSTAGE_E (3 * TILE_E)

// fused kvr tiles (128 m x 64 n): Ah, Al, 3x Bh
#define FA_E (128 * TSTR)
#define FB_E (64 * TSTR)
#define FSTAGE_E (2 * FA_E + 3 * FB_E)   // 17920 elems

// A fragment (m16n8k16 row): ldmatrix.x4 -> 4 regs
__device__ __forceinline__ void lda4(uint32_t* r, const f16* tile, int row0, int k0, int lane) {
    int row = row0 + (lane & 15);
    int col = k0 + ((lane & 16) >> 1);   // lanes 16-31 read k+8 half
    uint32_t a = smem_u32(tile + row * TSTR + col);
    asm volatile("ldmatrix.sync.aligned.m8n8.x4.shared.b16 {%0,%1,%2,%3}, [%4];"
        : "=r"(r[0]), "=r"(r[1]), "=r"(r[2]), "=r"(r[3]) : "r"(a));
}
// B fragments for two adjacent n8 tiles: ldmatrix.x4
__device__ __forceinline__ void ldb4(uint32_t* r, const f16* tile, int row0, int k0, int lane) {
    int row = row0 + (lane & 7) + ((lane & 16) >> 1);
    int col = k0 + (lane & 8);
    uint32_t a = smem_u32(tile + row * TSTR + col);
    asm volatile("ldmatrix.sync.aligned.m8n8.x4.shared.b16 {%0,%1,%2,%3}, [%4];"
        : "=r"(r[0]), "=r"(r[1]), "=r"(r[2]), "=r"(r[3]) : "r"(a));
}

// ---------------- prep kernels ----------------
// fp32 -> fp16 hi/lo split (for x)
__global__ void prep_split(const float* __restrict__ src, f16* __restrict__ dh,
                           f16* __restrict__ dl, int n4) {
    int i = blockIdx.x * blockDim.x + threadIdx.x;
    if (i >= n4) return;
    float4 v = ((const float4*)src)[i];
    float vv[4] = {v.x, v.y, v.z, v.w};
    uint16_t h[4], l[4];
#pragma unroll
    for (int q = 0; q < 4; q++) split2h(vv[q], h[q], l[q]);
    ((uint2*)dh)[i] = make_uint2((uint32_t)h[0] | ((uint32_t)h[1] << 16),
                                 (uint32_t)h[2] | ((uint32_t)h[3] << 16));
    ((uint2*)dl)[i] = make_uint2((uint32_t)l[0] | ((uint32_t)l[1] << 16),
                                 (uint32_t)l[2] | ((uint32_t)l[3] << 16));
}

// fp32 -> fp16 round only (for Wo)
__global__ void prep_round(const float* __restrict__ src, f16* __restrict__ dh, int n4) {
    int i = blockIdx.x * blockDim.x + threadIdx.x;
    if (i >= n4) return;
    float4 v = ((const float4*)src)[i];
    f16 h0 = __float2half_rn(v.x), h1 = __float2half_rn(v.y);
    f16 h2 = __float2half_rn(v.z), h3 = __float2half_rn(v.w);
    ((uint2*)dh)[i] = make_uint2((uint32_t)*(uint16_t*)&h0 | ((uint32_t)*(uint16_t*)&h1 << 16),
                                 (uint32_t)*(uint16_t*)&h2 | ((uint32_t)*(uint16_t*)&h3 << 16));
}

// scale Wk/Wv/Wr columns by time-mix, round to fp16
__global__ void prep_w(const float* __restrict__ Wk, const float* __restrict__ Wv,
                       const float* __restrict__ Wr, const float* __restrict__ tmk,
                       const float* __restrict__ tmv, const float* __restrict__ tmr) {
    int idx = blockIdx.x * blockDim.x + threadIdx.x;
    if (idx >= Dn * Dn / 4) return;
    int basei = idx * 4;
    int d = basei & (Dn - 1);
    const float* Ws[3] = {Wk, Wv, Wr};
    const float* Tm[3] = {tmk, tmv, tmr};
#pragma unroll
    for (int i = 0; i < 3; i++) {
        float4 w = *(const float4*)&Ws[i][basei];
        float4 mm = *(const float4*)&Tm[i][d];
        f16 h0 = __float2half_rn(w.x * mm.x), h1 = __float2half_rn(w.y * mm.y);
        f16 h2 = __float2half_rn(w.z * mm.z), h3 = __float2half_rn(w.w * mm.w);
        *(uint2*)&g_Wh[i][basei] =
            make_uint2((uint32_t)*(uint16_t*)&h0 | ((uint32_t)*(uint16_t*)&h1 << 16),
                       (uint32_t)*(uint16_t*)&h2 | ((uint32_t)*(uint16_t*)&h3 << 16));
    }
}

__global__ void prep_bias(const float* __restrict__ Wk, const float* __restrict__ Wv,
                          const float* __restrict__ Wr, const float* __restrict__ lx,
                          const float* __restrict__ tmk, const float* __restrict__ tmv,
                          const float* __restrict__ tmr) {
    __shared__ float red[256];
    int e = blockIdx.x;
    int t = threadIdx.x;
    const float* Ws[3] = {Wk, Wv, Wr};
    const float* tms[3] = {tmk, tmv, tmr};
#pragma unroll
    for (int i = 0; i < 3; i++) {
        float s = 0.f;
        for (int d = t; d < Dn; d += 256)
            s += Ws[i][(size_t)e * Dn + d] * lx[d] * (1.f - tms[i][d]);
        red[t] = s;
        __syncthreads();
        for (int off = 128; off > 0; off >>= 1) {
            if (t < off) red[t] += red[t + off];
            __syncthreads();
        }
        if (t == 0) g_b[i * Dn + e] = red[0];
        __syncthreads();
    }
}

// ---------------- fused k/v/r GEMM + WKV epilogue ----------------
// CTA tile: 128 m x 64 n. 8 warps, each owning 32x32 of ALL THREE outputs.
// 2-term fp16: c = Ah*Bh + Al*Bh
__global__ __launch_bounds__(256, 1)
void gemm_kvr_fused(const float* __restrict__ tf, const float* __restrict__ td,
                    const float* __restrict__ lnum, const float* __restrict__ lden,
                    float* __restrict__ out_num, float* __restrict__ out_den) {
    extern __shared__ f16 sm[];
    const int t = threadIdx.x;
    const int lane = t & 31, wid = t >> 5;
    const int e0 = blockIdx.x * 64, m0 = blockIdx.y * 128;

    uint32_t sbase = smem_u32(sm);

    auto stage_load = [&](int ch, int stg) {
        uint32_t s0 = sbase + stg * FSTAGE_E * 2;
        int kcol = ch * 32;
        // A tiles (128 rows): 512 thread-ops per tile -> 2 iters
#pragma unroll
        for (int i = 0; i < 2; i++) {
            int idx = t + i * 256;
            int row = idx >> 2, q = idx & 3;
            uint32_t soff = (uint32_t)(row * TSTR + q * 8) * 2;
            size_t g = (size_t)(m0 + row) * Dn + kcol + q * 8;
            cp16(s0 + soff,             g_xh + g);
            cp16(s0 + FA_E * 2 + soff,  g_xl + g);
        }
        // B tiles (64 rows): 256 thread-ops per tile, 3 matrices (hi only)
        {
            int row = t >> 2, q = t & 3;
            uint32_t soff = (uint32_t)(row * TSTR + q * 8) * 2;
            size_t g = (size_t)(e0 + row) * Dn + kcol + q * 8;
#pragma unroll
            for (int z = 0; z < 3; z++)
                cp16(s0 + (2 * FA_E + z * FB_E) * 2 + soff, &g_Wh[z][0] + g);
        }
    };

    float c[3][2][4][4];
#pragma unroll
    for (int z = 0; z < 3; z++)
#pragma unroll
        for (int i = 0; i < 2; i++)
#pragma unroll
            for (int j = 0; j < 4; j++)
#pragma unroll
                for (int q = 0; q < 4; q++) c[z][i][j][q] = 0.f;

    stage_load(0, 0); CP_COMMIT();
    stage_load(1, 1); CP_COMMIT();

    const int mw = (wid >> 1) * 32;   // warp m offset (0..96)
    const int nw = (wid & 1) * 32;    // warp n offset (0/32)

    for (int ch = 0; ch < NCH; ch++) {
        CP_WAIT1();
        __syncthreads();
        const f16* st  = sm + (ch & 1) * FSTAGE_E;
        const f16* tAh = st;
        const f16* tAl = st + FA_E;
#pragma unroll
        for (int s = 0; s < 2; s++) {
            int k0 = s * 16;
            uint32_t ah[2][4], al[2][4];
#pragma unroll
            for (int i = 0; i < 2; i++) {
                lda4(ah[i], tAh, mw + i * 16, k0, lane);
                lda4(al[i], tAl, mw + i * 16, k0, lane);
            }
#pragma unroll
            for (int z = 0; z < 3; z++) {
                const f16* tBh = st + 2 * FA_E + z * FB_E;
                uint32_t bh[2][4];
                ldb4(bh[0], tBh, nw, k0, lane);
                ldb4(bh[1], tBh, nw + 16, k0, lane);
#pragma unroll
                for (int i = 0; i < 2; i++)
#pragma unroll
                    for (int j = 0; j < 4; j++) {
                        uint32_t hb0 = bh[j >> 1][(j & 1) * 2], hb1 = bh[j >> 1][(j & 1) * 2 + 1];
                        MMA16816(c[z][i][j], ah[i], hb0, hb1);   // hi * B
                        MMA16816(c[z][i][j], al[i], hb0, hb1);   // lo * B
                    }
            }
        }
        __syncthreads();
        if (ch + 2 < NCH) stage_load(ch + 2, ch & 1);
        CP_COMMIT();
    }

    // ---- fused WKV epilogue (each warp owns all of k,v,r for its 32x32) ----
#pragma unroll
    for (int j = 0; j < 4; j++) {
        int e = e0 + nw + j * 8 + (lane & 3) * 2;   // two consecutive e: e, e+1
        float tf0 = tf[e],         tf1 = tf[e + 1];
        float bk0 = g_b[e],        bk1 = g_b[e + 1];
        float bv0 = g_b[Dn + e],   bv1 = g_b[Dn + e + 1];
        float br0 = g_b[2*Dn + e], br1 = g_b[2*Dn + e + 1];
        float ln0 = lnum[e],       ln1 = lnum[e + 1];
        float ld0 = lden[e],       ld1 = lden[e + 1];
#pragma unroll
        for (int i = 0; i < 2; i++) {
#pragma unroll
            for (int half = 0; half < 2; half++) {   // half 0: rows r, half 1: r+8
                int m = m0 + mw + i * 16 + (lane >> 2) + half * 8;
                int q0 = half * 2, q1 = half * 2 + 1;
                float kv0 = c[0][i][j][q0] + bk0, kv1 = c[0][i][j][q1] + bk1;
                float vv0 = c[1][i][j][q0] + bv0, vv1 = c[1][i][j][q1] + bv1;
                float rv0 = c[2][i][j][q0] + br0, rv1 = c[2][i][j][q1] + br1;
                float efk0 = expf(tf0 + kv0), efk1 = expf(tf1 + kv1);
                float wkv0 = (ln0 + efk0 * vv0) / (ld0 + efk0);
                float wkv1 = (ln1 + efk1 * vv1) / (ld1 + efk1);
                float val0 = wkv0 / (1.f + expf(-rv0));
                float val1 = wkv1 / (1.f + expf(-rv1));
                uint16_t h0, l0, h1, l1;
                split2h(val0, h0, l0);
                split2h(val1, h1, l1);
                size_t off = ((size_t)m * Dn + e) >> 1;   // u32 index
                ((uint32_t*)g_ah)[off] = (uint32_t)h0 | ((uint32_t)h1 << 16);
                ((uint32_t*)g_al)[off] = (uint32_t)l0 | ((uint32_t)l1 << 16);
                if ((m & (Tn - 1)) == (Tn - 1)) {
                    int bidx = m >> 12;
                    float ek0 = expf(kv0), ek1 = expf(kv1);
                    float dc0 = expf(-expf(td[e])), dc1 = expf(-expf(td[e + 1]));
                    out_num[bidx * Dn + e]     = dc0 * ln0 + ek0 * vv0;
                    out_num[bidx * Dn + e + 1] = dc1 * ln1 + ek1 * vv1;
                    out_den[bidx * Dn + e]     = dc0 * ld0 + ek0;
                    out_den[bidx * Dn + e + 1] = dc1 * ld1 + ek1;
                }
            }
        }
    }
}

// ---------------- out GEMM: out = rwkv @ Wo^T (128x128, 2-term fp16) ------
__global__ __launch_bounds__(256, 1)
void gemm_out_mma(float* __restrict__ outp) {
    extern __shared__ f16 sm[];
    const int t = threadIdx.x;
    const int lane = t & 31, wid = t >> 5;
    const int e0 = blockIdx.x * 128, m0 = blockIdx.y * 128;

    uint32_t sbase = smem_u32(sm);

    auto stage_load = [&](int ch, int stg) {
        uint32_t s0 = sbase + stg * OSTAGE_E * 2;
        int kcol = ch * 32;
#pragma unroll
        for (int i = 0; i < 2; i++) {
            int idx = t + i * 256;
            int row = idx >> 2, q = idx & 3;
            uint32_t soff = (uint32_t)(row * TSTR + q * 8) * 2;
            size_t goffA = (size_t)(m0 + row) * Dn + kcol + q * 8;
            size_t goffB = (size_t)(e0 + row) * Dn + kcol + q * 8;
            cp16(s0 + soff,               g_ah + goffA);
            cp16(s0 + TILE_E * 2 + soff,  g_al + goffA);
            cp16(s0 + TILE_E * 4 + soff,  g_Woh + goffB);
        }
    };

    float c[4][4][4];
#pragma unroll
    for (int i = 0; i < 4; i++)
#pragma unroll
        for (int j = 0; j < 4; j++)
#pragma unroll
            for (int q = 0; q < 4; q++) c[i][j][q] = 0.f;

    stage_load(0, 0); CP_COMMIT();
    stage_load(1, 1); CP_COMMIT();

    const int mw = (wid >> 2) * 64;
    const int nw = (wid & 3) * 32;

    for (int ch = 0; ch < NCH; ch++) {
        CP_WAIT1();
        __syncthreads();
        const f16* st  = sm + (ch & 1) * OSTAGE_E;
        const f16* tAh = st;
        const f16* tAl = st + TILE_E;
        const f16* tBh = st + 2 * TILE_E;
#pragma unroll
        for (int s = 0; s < 2; s++) {
            int k0 = s * 16;
            uint32_t ah[4][4], al[4][4], bh[2][4];
#pragma unroll
            for (int i = 0; i < 4; i++) {
                lda4(ah[i], tAh, mw + i * 16, k0, lane);
                lda4(al[i], tAl, mw + i * 16, k0, lane);
            }
#pragma unroll
            for (int jj = 0; jj < 2; jj++)
                ldb4(bh[jj], tBh, nw + jj * 16, k0, lane);
#pragma unroll
            for (int i = 0; i < 4; i++)
#pragma unroll
                for (int j = 0; j < 4; j++) {
                    uint32_t hb0 = bh[j >> 1][(j & 1) * 2], hb1 = bh[j >> 1][(j & 1) * 2 + 1];
                    MMA16816(c[i][j], ah[i], hb0, hb1);
                    MMA16816(c[i][j], al[i], hb0, hb1);
                }
        }
        __syncthreads();
        if (ch + 2 < NCH) stage_load(ch + 2, ch & 1);
        CP_COMMIT();
    }

#pragma unroll
    for (int i = 0; i < 4; i++) {
        int mrow = m0 + mw + i * 16 + (lane >> 2);
#pragma unroll
        for (int j = 0; j < 4; j++) {
            int ncol = e0 + nw + j * 8 + (lane & 3) * 2;
            *(float2*)&outp[(size_t)mrow * Dn + ncol] = make_float2(c[i][j][0], c[i][j][1]);
            *(float2*)&outp[(size_t)(mrow + 8) * Dn + ncol] = make_float2(c[i][j][2], c[i][j][3]);
        }
    }
}

// ---------------- tail ----------------
__global__ void tail_xlast(const float* __restrict__ x, float* __restrict__ out_x) {
    int i = blockIdx.x * blockDim.x + threadIdx.x;
    if (i < Bn * Dn) {
        int b = i / Dn;
        int d = i & (Dn - 1);
        out_x[i] = x[((size_t)b * Tn + (Tn - 1)) * Dn + d];
    }
}

// ---------------- launch ----------------
extern "C" void kernel_launch(void* const* d_in, const int* in_sizes, int n_in,
                              void* d_out, int out_size) {
    const float* x        = (const float*)d_in[0];
    const float* last_x   = (const float*)d_in[1];
    const float* last_num = (const float*)d_in[2];
    const float* last_den = (const float*)d_in[3];
    const float* td  = (const float*)d_in[4];
    const float* tf  = (const float*)d_in[5];
    const float* tmk = (const float*)d_in[6];
    const float* tmv = (const float*)d_in[7];
    const float* tmr = (const float*)d_in[8];
    const float* Wk  = (const float*)d_in[9];
    const float* Wv  = (const float*)d_in[10];
    const float* Wr  = (const float*)d_in[11];
    const float* Wo  = (const float*)d_in[12];

    float* out     = (float*)d_out;
    float* out_x   = out + (size_t)Mn * Dn;
    float* out_num = out_x + Bn * Dn;
    float* out_den = out_num + Bn * Dn;

    const int KVR_SMEM = 2 * FSTAGE_E * 2;   // 71680 bytes
    const int OUT_SMEM = 2 * OSTAGE_E * 2;   // 61440 bytes
    cudaFuncSetAttribute(gemm_kvr_fused, cudaFuncAttributeMaxDynamicSharedMemorySize, KVR_SMEM);
    cudaFuncSetAttribute(gemm_out_mma, cudaFuncAttributeMaxDynamicSharedMemorySize, OUT_SMEM);

    f16 *p_xh, *p_xl, *p_woh;
    cudaGetSymbolAddress((void**)&p_xh, g_xh);
    cudaGetSymbolAddress((void**)&p_xl, g_xl);
    cudaGetSymbolAddress((void**)&p_woh, g_Woh);

    // prep
    prep_w<<<(Dn * Dn / 4 + 255) / 256, 256>>>(Wk, Wv, Wr, tmk, tmv, tmr);
    prep_round<<<(Dn * Dn / 4 + 255) / 256, 256>>>(Wo, p_woh, Dn * Dn / 4);
    prep_split<<<(Mn * Dn / 4 + 255) / 256, 256>>>(x, p_xh, p_xl, Mn * Dn / 4);
    prep_bias<<<Dn, 256>>>(Wk, Wv, Wr, last_x, tmk, tmv, tmr);

    // fused k/v/r GEMM + WKV epilogue
    dim3 grid_kvr(Dn / 64, Mn / 128);   // (16, 128) = 2048 CTAs
    gemm_kvr_fused<<<grid_kvr, 256, KVR_SMEM>>>(tf, td, last_num, last_den, out_num, out_den);

    // output GEMM
    dim3 grid_out(Dn / 128, Mn / 128);  // (8, 128) = 1024 CTAs
    gemm_out_mma<<<grid_out, 256, OUT_SMEM>>>(out);

    tail_xlast<<<(Bn * Dn + 255) / 256, 256>>>(x, out_x);
}